// round 4
// baseline (speedup 1.0000x reference)
#include <cuda_runtime.h>
#include <cuda_bf16.h>
#include <cstdint>

#define TT 2048
#define BB 16
#define DD 1024
#define NN 64
#define MT (TT * BB)      // 32768 rows
#define NC 256            // k|v|q|a packed columns

// ------------------------- device scratch (no allocs allowed) ---------------
__device__ float g_proj[(size_t)MT * NC];                 // 32 MB
__device__ __nv_bfloat16 g_xhi[(size_t)MT * DD];          // 64 MB
__device__ __nv_bfloat16 g_xlo[(size_t)MT * DD];          // 64 MB
__device__ __nv_bfloat16 g_whi[(size_t)NC * DD];          // 512 KB
__device__ __nv_bfloat16 g_wlo[(size_t)NC * DD];          // 512 KB

// ---------------------------------------------------------------------------
// Convert X -> bf16 hi/lo split.  x = hi + lo + O(2^-18 * |x|)
// ---------------------------------------------------------------------------
__global__ __launch_bounds__(256) void convert_x(const float* __restrict__ x) {
    size_t t = (size_t)blockIdx.x * blockDim.x + threadIdx.x;   // one per 16 elems
    size_t base = t * 16;
#pragma unroll
    for (int l = 0; l < 4; l++) {
        float4 v = *(const float4*)(x + base + l * 4);
        __nv_bfloat16 h0 = __float2bfloat16(v.x);
        __nv_bfloat16 h1 = __float2bfloat16(v.y);
        __nv_bfloat16 h2 = __float2bfloat16(v.z);
        __nv_bfloat16 h3 = __float2bfloat16(v.w);
        __nv_bfloat16 l0 = __float2bfloat16(v.x - __bfloat162float(h0));
        __nv_bfloat16 l1 = __float2bfloat16(v.y - __bfloat162float(h1));
        __nv_bfloat16 l2 = __float2bfloat16(v.z - __bfloat162float(h2));
        __nv_bfloat16 l3 = __float2bfloat16(v.w - __bfloat162float(h3));
        __nv_bfloat162 hp0 = __halves2bfloat162(h0, h1);
        __nv_bfloat162 hp1 = __halves2bfloat162(h2, h3);
        __nv_bfloat162 lp0 = __halves2bfloat162(l0, l1);
        __nv_bfloat162 lp1 = __halves2bfloat162(l2, l3);
        *(uint2*)&g_xhi[base + l * 4] = make_uint2(*(uint32_t*)&hp0, *(uint32_t*)&hp1);
        *(uint2*)&g_xlo[base + l * 4] = make_uint2(*(uint32_t*)&lp0, *(uint32_t*)&lp1);
    }
}

// Convert W (4 matrices, stacked into 256 rows: k|v|q|a) -> bf16 hi/lo
__global__ __launch_bounds__(256) void convert_w(
    const float* __restrict__ Wk, const float* __restrict__ Wv,
    const float* __restrict__ Wq, const float* __restrict__ Wa)
{
    int e4 = blockIdx.x * 256 + threadIdx.x;   // one per float4; 65536 total
    int base = e4 * 4;
    int row = base >> 10;       // 0..255
    int colk = base & 1023;
    int cb = row >> 6, n = row & 63;
    const float* W = (cb == 0) ? Wk : (cb == 1) ? Wv : (cb == 2) ? Wq : Wa;
    float4 v = *(const float4*)(W + (size_t)n * DD + colk);
    __nv_bfloat16 h0 = __float2bfloat16(v.x);
    __nv_bfloat16 h1 = __float2bfloat16(v.y);
    __nv_bfloat16 h2 = __float2bfloat16(v.z);
    __nv_bfloat16 h3 = __float2bfloat16(v.w);
    __nv_bfloat16 l0 = __float2bfloat16(v.x - __bfloat162float(h0));
    __nv_bfloat16 l1 = __float2bfloat16(v.y - __bfloat162float(h1));
    __nv_bfloat16 l2 = __float2bfloat16(v.z - __bfloat162float(h2));
    __nv_bfloat16 l3 = __float2bfloat16(v.w - __bfloat162float(h3));
    __nv_bfloat162 hp0 = __halves2bfloat162(h0, h1);
    __nv_bfloat162 hp1 = __halves2bfloat162(h2, h3);
    __nv_bfloat162 lp0 = __halves2bfloat162(l0, l1);
    __nv_bfloat162 lp1 = __halves2bfloat162(l2, l3);
    *(uint2*)&g_whi[(size_t)row * DD + colk] = make_uint2(*(uint32_t*)&hp0, *(uint32_t*)&hp1);
    *(uint2*)&g_wlo[(size_t)row * DD + colk] = make_uint2(*(uint32_t*)&lp0, *(uint32_t*)&lp1);
}

// ---------------------------------------------------------------------------
// Tensor-core GEMM: g_proj[32768,256] = X[32768,1024] @ Wcat^T
// 3x bf16 split: hh + hl + lh, fp32 accumulate via mma.sync.m16n8k16
// ---------------------------------------------------------------------------
#define GBM 128
#define GBN 128
#define GBK 32
#define SA  40    // smem row stride in bf16

#define MMA16816(d, a, b0v, b1v)                                              \
    asm volatile("mma.sync.aligned.m16n8k16.row.col.f32.bf16.bf16.f32 "       \
                 "{%0,%1,%2,%3}, {%4,%5,%6,%7}, {%8,%9}, {%0,%1,%2,%3};"      \
                 : "+f"(d[0]), "+f"(d[1]), "+f"(d[2]), "+f"(d[3])             \
                 : "r"(a[0]), "r"(a[1]), "r"(a[2]), "r"(a[3]),                \
                   "r"(b0v), "r"(b1v));

__global__ __launch_bounds__(256) void mma_gemm() {
    __shared__ alignas(16) __nv_bfloat16 Ah[GBM * SA];
    __shared__ alignas(16) __nv_bfloat16 Al[GBM * SA];
    __shared__ alignas(16) __nv_bfloat16 Bh[GBN * SA];
    __shared__ alignas(16) __nv_bfloat16 Bl[GBN * SA];

    const int tid = threadIdx.x;
    const int wid = tid >> 5, lane = tid & 31;
    const int wm = wid & 3, wn = wid >> 2;        // warp tile at (wm*32, wn*64)
    const int row0 = blockIdx.x * GBM;
    const int col0 = blockIdx.y * GBN;
    const int g = lane >> 2, tg = lane & 3;       // groupID, threadInGroup

    float acc[2][8][4];
#pragma unroll
    for (int a = 0; a < 2; a++)
#pragma unroll
        for (int b = 0; b < 8; b++)
#pragma unroll
            for (int r = 0; r < 4; r++) acc[a][b][r] = 0.f;

    for (int kb = 0; kb < DD; kb += GBK) {
#pragma unroll
        for (int l = 0; l < 2; l++) {
            int f = tid + 256 * l;          // 0..511
            int r = f >> 2, kc = f & 3;     // row 0..127, 8-elem chunk 0..3
            size_t ga = (size_t)(row0 + r) * DD + kb + kc * 8;
            size_t gb = (size_t)(col0 + r) * DD + kb + kc * 8;
            *(uint4*)&Ah[r * SA + kc * 8] = *(const uint4*)&g_xhi[ga];
            *(uint4*)&Al[r * SA + kc * 8] = *(const uint4*)&g_xlo[ga];
            *(uint4*)&Bh[r * SA + kc * 8] = *(const uint4*)&g_whi[gb];
            *(uint4*)&Bl[r * SA + kc * 8] = *(const uint4*)&g_wlo[gb];
        }
        __syncthreads();

#pragma unroll
        for (int ks = 0; ks < GBK; ks += 16) {
            uint32_t afh[2][4], afl[2][4];
            const int kk2 = ks + 2 * tg;
#pragma unroll
            for (int ms = 0; ms < 2; ms++) {
                int rr = wm * 32 + ms * 16 + g;
                afh[ms][0] = *(const uint32_t*)&Ah[rr * SA + kk2];
                afh[ms][1] = *(const uint32_t*)&Ah[(rr + 8) * SA + kk2];
                afh[ms][2] = *(const uint32_t*)&Ah[rr * SA + kk2 + 8];
                afh[ms][3] = *(const uint32_t*)&Ah[(rr + 8) * SA + kk2 + 8];
                afl[ms][0] = *(const uint32_t*)&Al[rr * SA + kk2];
                afl[ms][1] = *(const uint32_t*)&Al[(rr + 8) * SA + kk2];
                afl[ms][2] = *(const uint32_t*)&Al[rr * SA + kk2 + 8];
                afl[ms][3] = *(const uint32_t*)&Al[(rr + 8) * SA + kk2 + 8];
            }
#pragma unroll
            for (int ns = 0; ns < 8; ns++) {
                int nr = wn * 64 + ns * 8 + g;
                uint32_t bh0 = *(const uint32_t*)&Bh[nr * SA + kk2];
                uint32_t bh1 = *(const uint32_t*)&Bh[nr * SA + kk2 + 8];
                uint32_t bl0 = *(const uint32_t*)&Bl[nr * SA + kk2];
                uint32_t bl1 = *(const uint32_t*)&Bl[nr * SA + kk2 + 8];
#pragma unroll
                for (int ms = 0; ms < 2; ms++) {
                    MMA16816(acc[ms][ns], afh[ms], bh0, bh1);
                    MMA16816(acc[ms][ns], afh[ms], bl0, bl1);
                    MMA16816(acc[ms][ns], afl[ms], bh0, bh1);
                }
            }
        }
        __syncthreads();
    }

#pragma unroll
    for (int ms = 0; ms < 2; ms++)
#pragma unroll
        for (int ns = 0; ns < 8; ns++) {
            int m = row0 + wm * 32 + ms * 16 + g;
            int n = col0 + wn * 64 + ns * 8 + tg * 2;
            *(float2*)&g_proj[(size_t)m * NC + n] =
                make_float2(acc[ms][ns][0], acc[ms][ns][1]);
            *(float2*)&g_proj[(size_t)(m + 8) * NC + n] =
                make_float2(acc[ms][ns][2], acc[ms][ns][3]);
        }
}

// ---------------------------------------------------------------------------
// Sequential scan, v3.
//  - 32 blocks x 256 threads (8 warps): block = 32 rows of one batch,
//    8 lanes per row. 2 blocks per batch -> 2 warps/SMSP for stall overlap.
//  - Reduce pipelined OFF the chain: dots for r_{t+1} are issued at the end
//    of step t using pre-update S (identity r_{t+1} = a*(S.k') + cc*(k.k')),
//    giving the shfl tree a full step of slack. Chain = gate + 2 fma.
// ---------------------------------------------------------------------------
__device__ __forceinline__ float fast_tanh(float x) {
    float r;
    asm("tanh.approx.f32 %0, %1;" : "=f"(r) : "f"(x));
    return r;
}

__global__ __launch_bounds__(256) void scan_kernel(
    const float* __restrict__ S_in,
    const float* __restrict__ dA,
    const float* __restrict__ bA,
    float* __restrict__ out)   // [T*B*N] output, then [B*N*N] S_final
{
    const int b  = blockIdx.x >> 1;
    const int rb = blockIdx.x & 1;
    const int il = threadIdx.x >> 3;     // local row 0..31
    const int i  = rb * 32 + il;         // global row 0..63
    const int c  = threadIdx.x & 7;      // lane within row
    const int j0 = c << 3;

    float S[8];
    {
        const float* sp = S_in + ((size_t)b * NN + i) * NN + j0;
#pragma unroll
        for (int r = 0; r < 8; r++) S[r] = sp[r];
    }
    const float da = dA[i];
    const float ba = bA[i];

    float kb_[4][8], qb_[4][8], vb_[4], ab_[4];

    auto ldrow = [&](int t, int ph) {
        const float* P = g_proj + (size_t)(t * BB + b) * NC;
        float4 f0 = *(const float4*)(P + j0);
        float4 f1 = *(const float4*)(P + j0 + 4);
        kb_[ph][0] = f0.x; kb_[ph][1] = f0.y; kb_[ph][2] = f0.z; kb_[ph][3] = f0.w;
        kb_[ph][4] = f1.x; kb_[ph][5] = f1.y; kb_[ph][6] = f1.z; kb_[ph][7] = f1.w;
        float4 g0 = *(const float4*)(P + 128 + j0);
        float4 g1 = *(const float4*)(P + 128 + j0 + 4);
        qb_[ph][0] = g0.x; qb_[ph][1] = g0.y; qb_[ph][2] = g0.z; qb_[ph][3] = g0.w;
        qb_[ph][4] = g1.x; qb_[ph][5] = g1.y; qb_[ph][6] = g1.z; qb_[ph][7] = g1.w;
        vb_[ph] = P[64 + i];
        ab_[ph] = P[192 + i];
    };

    ldrow(0, 0); ldrow(1, 1); ldrow(2, 2);

    // r_0 = S_init . k_0
    float r = 0.f;
#pragma unroll
    for (int j = 0; j < 8; j++) r = fmaf(S[j], kb_[0][j], r);
    r += __shfl_xor_sync(0xFFFFFFFFu, r, 1);
    r += __shfl_xor_sync(0xFFFFFFFFu, r, 2);
    r += __shfl_xor_sync(0xFFFFFFFFu, r, 4);

    // pending dots for r_1: d1p = S_init . k_1, up = k_0 . k_1
    float d1p = 0.f, up = 0.f;
#pragma unroll
    for (int j = 0; j < 8; j++) {
        d1p = fmaf(S[j], kb_[1][j], d1p);
        up  = fmaf(kb_[0][j], kb_[1][j], up);
    }
    d1p += __shfl_xor_sync(0xFFFFFFFFu, d1p, 1);
    up  += __shfl_xor_sync(0xFFFFFFFFu, up, 1);
    d1p += __shfl_xor_sync(0xFFFFFFFFu, d1p, 2);
    up  += __shfl_xor_sync(0xFFFFFFFFu, up, 2);
    d1p += __shfl_xor_sync(0xFFFFFFFFu, d1p, 4);
    up  += __shfl_xor_sync(0xFFFFFFFFu, up, 4);

    auto step = [&](int t, int ph) {
        const float* kc = kb_[ph];
        const float* qc = qb_[ph];
        const float vc = vb_[ph];

        // --- critical chain: r -> alpha -> cc / r_next ---
        float xg = fmaf(da, r, ab_[ph] + ba);
        float alpha = fmaf(0.5f, fast_tanh(0.5f * xg), 0.5f);
        float cc = (1.0f - alpha) * vc;
        r = fmaf(alpha, d1p, cc * up);        // r_{t+1}, pending dots ready

        // --- S update + out dot ---
        float o = 0.f;
#pragma unroll
        for (int j = 0; j < 8; j++) {
            S[j] = fmaf(alpha, S[j], cc * kc[j]);
            o = fmaf(S[j], qc[j], o);
        }

        // --- issue NEXT step's dots (slack = one full step) ---
        // r_{t+2} = alpha_{t+1} * (S_t . k_{t+2}) + cc_{t+1} * (k_{t+1} . k_{t+2})
        const float* k1 = kb_[(ph + 1) & 3];
        const float* k2 = kb_[(ph + 2) & 3];
        float d = 0.f, u = 0.f;
#pragma unroll
        for (int j = 0; j < 8; j++) {
            d = fmaf(S[j], k2[j], d);
            u = fmaf(k1[j], k2[j], u);
        }
        d += __shfl_xor_sync(0xFFFFFFFFu, d, 1);
        u += __shfl_xor_sync(0xFFFFFFFFu, u, 1);
        d += __shfl_xor_sync(0xFFFFFFFFu, d, 2);
        u += __shfl_xor_sync(0xFFFFFFFFu, u, 2);
        d += __shfl_xor_sync(0xFFFFFFFFu, d, 4);
        u += __shfl_xor_sync(0xFFFFFFFFu, u, 4);
        d1p = d; up = u;

        // --- o reduce + output (fully off-chain) ---
        o += __shfl_xor_sync(0xFFFFFFFFu, o, 1);
        o += __shfl_xor_sync(0xFFFFFFFFu, o, 2);
        o += __shfl_xor_sync(0xFFFFFFFFu, o, 4);
        if (c == 0) {
            float sig = fmaf(0.5f, fast_tanh(0.5f * o), 0.5f);
            out[(size_t)(t * BB + b) * NN + i] = o * o * sig;   // o * silu(o)
        }

        // --- prefetch t+3 into the slot that held t-1 ---
        int tp = t + 3; if (tp > TT - 1) tp = TT - 1;
        ldrow(tp, (ph + 3) & 3);
    };

    for (int t0 = 0; t0 < TT; t0 += 4) {
        step(t0 + 0, 0);
        step(t0 + 1, 1);
        step(t0 + 2, 2);
        step(t0 + 3, 3);
    }

    float* so = out + (size_t)TT * BB * NN + ((size_t)b * NN + i) * NN + j0;
#pragma unroll
    for (int rji = 0; rji < 8; rji++) so[rji] = S[rji];
}

extern "C" void kernel_launch(void* const* d_in, const int* in_sizes, int n_in,
                              void* d_out, int out_size) {
    const float* x  = (const float*)d_in[0];
    const float* S  = (const float*)d_in[1];
    const float* Wk = (const float*)d_in[2];
    const float* Wv = (const float*)d_in[3];
    const float* Wq = (const float*)d_in[4];
    const float* Wa = (const float*)d_in[5];
    const float* da = (const float*)d_in[6];
    const float* ba = (const float*)d_in[7];
    float* out = (float*)d_out;

    convert_x<<<MT * DD / (256 * 16), 256>>>(x);
    convert_w<<<NC * DD / (256 * 4), 256>>>(Wk, Wv, Wq, Wa);
    dim3 ggrid(MT / GBM, NC / GBN);
    mma_gemm<<<ggrid, 256>>>();
    scan_kernel<<<BB * 2, 256>>>(S, da, ba, out);
}

// round 5
// speedup vs baseline: 1.5225x; 1.5225x over previous
#include <cuda_runtime.h>
#include <cuda_bf16.h>
#include <cstdint>

#define TT 2048
#define BB 16
#define DD 1024
#define NN 64
#define MT (TT * BB)      // 32768 rows
#define NC 256            // k|v|q|a packed columns

// ------------------------- device scratch (no allocs allowed) ---------------
__device__ float g_proj[(size_t)MT * NC];                 // 32 MB
__device__ float g_gram[(size_t)MT * 8];                  // 1 MB
__device__ __nv_bfloat16 g_xhi[(size_t)MT * DD];          // 64 MB
__device__ __nv_bfloat16 g_xlo[(size_t)MT * DD];          // 64 MB
__device__ __nv_bfloat16 g_whi[(size_t)NC * DD];          // 512 KB
__device__ __nv_bfloat16 g_wlo[(size_t)NC * DD];          // 512 KB

// ---------------------------------------------------------------------------
// Convert X -> bf16 hi/lo split.  x = hi + lo + O(2^-18 * |x|)
// ---------------------------------------------------------------------------
__global__ __launch_bounds__(256) void convert_x(const float* __restrict__ x) {
    size_t t = (size_t)blockIdx.x * blockDim.x + threadIdx.x;
    size_t base = t * 16;
#pragma unroll
    for (int l = 0; l < 4; l++) {
        float4 v = *(const float4*)(x + base + l * 4);
        __nv_bfloat16 h0 = __float2bfloat16(v.x);
        __nv_bfloat16 h1 = __float2bfloat16(v.y);
        __nv_bfloat16 h2 = __float2bfloat16(v.z);
        __nv_bfloat16 h3 = __float2bfloat16(v.w);
        __nv_bfloat16 l0 = __float2bfloat16(v.x - __bfloat162float(h0));
        __nv_bfloat16 l1 = __float2bfloat16(v.y - __bfloat162float(h1));
        __nv_bfloat16 l2 = __float2bfloat16(v.z - __bfloat162float(h2));
        __nv_bfloat16 l3 = __float2bfloat16(v.w - __bfloat162float(h3));
        __nv_bfloat162 hp0 = __halves2bfloat162(h0, h1);
        __nv_bfloat162 hp1 = __halves2bfloat162(h2, h3);
        __nv_bfloat162 lp0 = __halves2bfloat162(l0, l1);
        __nv_bfloat162 lp1 = __halves2bfloat162(l2, l3);
        *(uint2*)&g_xhi[base + l * 4] = make_uint2(*(uint32_t*)&hp0, *(uint32_t*)&hp1);
        *(uint2*)&g_xlo[base + l * 4] = make_uint2(*(uint32_t*)&lp0, *(uint32_t*)&lp1);
    }
}

__global__ __launch_bounds__(256) void convert_w(
    const float* __restrict__ Wk, const float* __restrict__ Wv,
    const float* __restrict__ Wq, const float* __restrict__ Wa)
{
    int e4 = blockIdx.x * 256 + threadIdx.x;
    int base = e4 * 4;
    int row = base >> 10;
    int colk = base & 1023;
    int cb = row >> 6, n = row & 63;
    const float* W = (cb == 0) ? Wk : (cb == 1) ? Wv : (cb == 2) ? Wq : Wa;
    float4 v = *(const float4*)(W + (size_t)n * DD + colk);
    __nv_bfloat16 h0 = __float2bfloat16(v.x);
    __nv_bfloat16 h1 = __float2bfloat16(v.y);
    __nv_bfloat16 h2 = __float2bfloat16(v.z);
    __nv_bfloat16 h3 = __float2bfloat16(v.w);
    __nv_bfloat16 l0 = __float2bfloat16(v.x - __bfloat162float(h0));
    __nv_bfloat16 l1 = __float2bfloat16(v.y - __bfloat162float(h1));
    __nv_bfloat16 l2 = __float2bfloat16(v.z - __bfloat162float(h2));
    __nv_bfloat16 l3 = __float2bfloat16(v.w - __bfloat162float(h3));
    __nv_bfloat162 hp0 = __halves2bfloat162(h0, h1);
    __nv_bfloat162 hp1 = __halves2bfloat162(h2, h3);
    __nv_bfloat162 lp0 = __halves2bfloat162(l0, l1);
    __nv_bfloat162 lp1 = __halves2bfloat162(l2, l3);
    *(uint2*)&g_whi[(size_t)row * DD + colk] = make_uint2(*(uint32_t*)&hp0, *(uint32_t*)&hp1);
    *(uint2*)&g_wlo[(size_t)row * DD + colk] = make_uint2(*(uint32_t*)&lp0, *(uint32_t*)&lp1);
}

// ---------------------------------------------------------------------------
// Tensor-core GEMM (unchanged from R3): g_proj = X @ Wcat^T, 3x bf16 split.
// ---------------------------------------------------------------------------
#define GBM 128
#define GBN 128
#define GBK 32
#define SA  40

#define MMA16816(d, a, b0v, b1v)                                              \
    asm volatile("mma.sync.aligned.m16n8k16.row.col.f32.bf16.bf16.f32 "       \
                 "{%0,%1,%2,%3}, {%4,%5,%6,%7}, {%8,%9}, {%0,%1,%2,%3};"      \
                 : "+f"(d[0]), "+f"(d[1]), "+f"(d[2]), "+f"(d[3])             \
                 : "r"(a[0]), "r"(a[1]), "r"(a[2]), "r"(a[3]),                \
                   "r"(b0v), "r"(b1v));

__global__ __launch_bounds__(256) void mma_gemm() {
    __shared__ alignas(16) __nv_bfloat16 Ah[GBM * SA];
    __shared__ alignas(16) __nv_bfloat16 Al[GBM * SA];
    __shared__ alignas(16) __nv_bfloat16 Bh[GBN * SA];
    __shared__ alignas(16) __nv_bfloat16 Bl[GBN * SA];

    const int tid = threadIdx.x;
    const int wid = tid >> 5, lane = tid & 31;
    const int wm = wid & 3, wn = wid >> 2;
    const int row0 = blockIdx.x * GBM;
    const int col0 = blockIdx.y * GBN;
    const int g = lane >> 2, tg = lane & 3;

    float acc[2][8][4];
#pragma unroll
    for (int a = 0; a < 2; a++)
#pragma unroll
        for (int b = 0; b < 8; b++)
#pragma unroll
            for (int r = 0; r < 4; r++) acc[a][b][r] = 0.f;

    for (int kb = 0; kb < DD; kb += GBK) {
#pragma unroll
        for (int l = 0; l < 2; l++) {
            int f = tid + 256 * l;
            int r = f >> 2, kc = f & 3;
            size_t ga = (size_t)(row0 + r) * DD + kb + kc * 8;
            size_t gb = (size_t)(col0 + r) * DD + kb + kc * 8;
            *(uint4*)&Ah[r * SA + kc * 8] = *(const uint4*)&g_xhi[ga];
            *(uint4*)&Al[r * SA + kc * 8] = *(const uint4*)&g_xlo[ga];
            *(uint4*)&Bh[r * SA + kc * 8] = *(const uint4*)&g_whi[gb];
            *(uint4*)&Bl[r * SA + kc * 8] = *(const uint4*)&g_wlo[gb];
        }
        __syncthreads();

#pragma unroll
        for (int ks = 0; ks < GBK; ks += 16) {
            uint32_t afh[2][4], afl[2][4];
            const int kk2 = ks + 2 * tg;
#pragma unroll
            for (int ms = 0; ms < 2; ms++) {
                int rr = wm * 32 + ms * 16 + g;
                afh[ms][0] = *(const uint32_t*)&Ah[rr * SA + kk2];
                afh[ms][1] = *(const uint32_t*)&Ah[(rr + 8) * SA + kk2];
                afh[ms][2] = *(const uint32_t*)&Ah[rr * SA + kk2 + 8];
                afh[ms][3] = *(const uint32_t*)&Ah[(rr + 8) * SA + kk2 + 8];
                afl[ms][0] = *(const uint32_t*)&Al[rr * SA + kk2];
                afl[ms][1] = *(const uint32_t*)&Al[(rr + 8) * SA + kk2];
                afl[ms][2] = *(const uint32_t*)&Al[rr * SA + kk2 + 8];
                afl[ms][3] = *(const uint32_t*)&Al[(rr + 8) * SA + kk2 + 8];
            }
#pragma unroll
            for (int ns = 0; ns < 8; ns++) {
                int nr = wn * 64 + ns * 8 + g;
                uint32_t bh0 = *(const uint32_t*)&Bh[nr * SA + kk2];
                uint32_t bh1 = *(const uint32_t*)&Bh[nr * SA + kk2 + 8];
                uint32_t bl0 = *(const uint32_t*)&Bl[nr * SA + kk2];
                uint32_t bl1 = *(const uint32_t*)&Bl[nr * SA + kk2 + 8];
#pragma unroll
                for (int ms = 0; ms < 2; ms++) {
                    MMA16816(acc[ms][ns], afh[ms], bh0, bh1);
                    MMA16816(acc[ms][ns], afh[ms], bl0, bl1);
                    MMA16816(acc[ms][ns], afl[ms], bh0, bh1);
                }
            }
        }
        __syncthreads();
    }

#pragma unroll
    for (int ms = 0; ms < 2; ms++)
#pragma unroll
        for (int ns = 0; ns < 8; ns++) {
            int m = row0 + wm * 32 + ms * 16 + g;
            int n = col0 + wn * 64 + ns * 8 + tg * 2;
            *(float2*)&g_proj[(size_t)m * NC + n] =
                make_float2(acc[ms][ns][0], acc[ms][ns][1]);
            *(float2*)&g_proj[(size_t)(m + 8) * NC + n] =
                make_float2(acc[ms][ns][2], acc[ms][ns][3]);
        }
}

// ---------------------------------------------------------------------------
// Gram kernel: for each row r = t*16+b, compute
//   [kk1,kk2,kk3, kq0, kq1,kq2, 0,0] where kkd = k_t . k_{t+d}, kqd = k_t . q_{t+d}
// One warp per row; out-of-range -> 0.
// ---------------------------------------------------------------------------
__global__ __launch_bounds__(256) void gram_kernel() {
    const int wid = threadIdx.x >> 5, lane = threadIdx.x & 31;
    const int row = blockIdx.x * 8 + wid;
    const float* P0 = g_proj + (size_t)row * NC;

    float k0a = P0[lane], k0b = P0[32 + lane];
    float d[6];
    d[3] = k0a * P0[128 + lane] + k0b * P0[160 + lane];    // kq0
#pragma unroll
    for (int dd = 1; dd <= 3; dd++) {
        if (row + dd * BB < MT) {
            const float* Pd = g_proj + (size_t)(row + dd * BB) * NC;
            d[dd - 1] = k0a * Pd[lane] + k0b * Pd[32 + lane];           // kk_d
            if (dd <= 2)
                d[3 + dd] = k0a * Pd[128 + lane] + k0b * Pd[160 + lane]; // kq_d
        } else {
            d[dd - 1] = 0.f;
            if (dd <= 2) d[3 + dd] = 0.f;
        }
    }
#pragma unroll
    for (int m = 1; m < 32; m <<= 1)
#pragma unroll
        for (int e = 0; e < 6; e++)
            d[e] += __shfl_xor_sync(0xFFFFFFFFu, d[e], m);

    if (lane == 0) {
        float4* G = (float4*)&g_gram[(size_t)row * 8];
        G[0] = make_float4(d[0], d[1], d[2], d[3]);
        G[1] = make_float4(d[4], d[5], 0.f, 0.f);
    }
}

// ---------------------------------------------------------------------------
// Scan v4: reduction-free recurrence.
// Maintain scalars (per b,i):  r = S.k_t, E1..E3 = S.k_{t+1..3}, F0..F2 = S.q_{t..t+2}
// Per step: gate; 6 scalar 2-FMA updates using precomputed Gram terms;
// S row update; two off-chain trees refresh the deep horizon (S.k_{t+4}, S.q_{t+3}).
// Critical chain = gate + 1 FMA (~44 cyc). 32 blocks x 256 thr, 8 lanes/row.
// ---------------------------------------------------------------------------
__device__ __forceinline__ float fast_tanh(float x) {
    float r;
    asm("tanh.approx.f32 %0, %1;" : "=f"(r) : "f"(x));
    return r;
}

__global__ __launch_bounds__(256) void scan_kernel(
    const float* __restrict__ S_in,
    const float* __restrict__ dA,
    const float* __restrict__ bA,
    float* __restrict__ out)
{
    const int b  = blockIdx.x >> 1;
    const int rb = blockIdx.x & 1;
    const int il = threadIdx.x >> 3;
    const int i  = rb * 32 + il;
    const int c  = threadIdx.x & 7;
    const int j0 = c << 3;

    float S[8];
    {
        const float* sp = S_in + ((size_t)b * NN + i) * NN + j0;
#pragma unroll
        for (int r = 0; r < 8; r++) S[r] = sp[r];
    }
    const float da = dA[i];
    const float ba_ = bA[i];

    float kr[8][8], qr[4][8], gr[4][8], vr[4], ar[4];

    auto ldk = [&](int t, int slot) {
        const float* P = g_proj + (size_t)(t * BB + b) * NC + j0;
        float4 f0 = *(const float4*)P;
        float4 f1 = *(const float4*)(P + 4);
        kr[slot][0] = f0.x; kr[slot][1] = f0.y; kr[slot][2] = f0.z; kr[slot][3] = f0.w;
        kr[slot][4] = f1.x; kr[slot][5] = f1.y; kr[slot][6] = f1.z; kr[slot][7] = f1.w;
    };
    auto ldq = [&](int t, int slot) {
        const float* P = g_proj + (size_t)(t * BB + b) * NC + 128 + j0;
        float4 f0 = *(const float4*)P;
        float4 f1 = *(const float4*)(P + 4);
        qr[slot][0] = f0.x; qr[slot][1] = f0.y; qr[slot][2] = f0.z; qr[slot][3] = f0.w;
        qr[slot][4] = f1.x; qr[slot][5] = f1.y; qr[slot][6] = f1.z; qr[slot][7] = f1.w;
    };
    auto ldg_ = [&](int t, int slot) {
        const float* G = g_gram + (size_t)(t * BB + b) * 8;
        float4 g0 = *(const float4*)G;
        float4 g1 = *(const float4*)(G + 4);
        gr[slot][0] = g0.x; gr[slot][1] = g0.y; gr[slot][2] = g0.z; gr[slot][3] = g0.w;
        gr[slot][4] = g1.x; gr[slot][5] = g1.y; gr[slot][6] = g1.z; gr[slot][7] = g1.w;
    };
    auto ldva = [&](int t, int slot) {
        const float* P = g_proj + (size_t)(t * BB + b) * NC;
        vr[slot] = P[64 + i];
        ar[slot] = P[192 + i] + ba_;
    };

    // preload rings
#pragma unroll
    for (int s = 0; s < 8; s++) ldk(s, s);
    ldq(3, 3); ldq(4, 0); ldq(5, 1); ldq(6, 2);
#pragma unroll
    for (int s = 0; s < 4; s++) { ldg_(s, s); ldva(s, s); }

    // prologue: r = S.k0, E1..E3 = S.k_{1..3}, F0..F2 = S.q_{0..2}
    float r, E1, E2, E3, F0, F1, F2;
    {
        float p[7] = {0.f, 0.f, 0.f, 0.f, 0.f, 0.f, 0.f};
        float tq[3][8];
#pragma unroll
        for (int s = 0; s < 3; s++) {
            const float* P = g_proj + (size_t)(s * BB + b) * NC + 128 + j0;
            float4 f0 = *(const float4*)P;
            float4 f1 = *(const float4*)(P + 4);
            tq[s][0] = f0.x; tq[s][1] = f0.y; tq[s][2] = f0.z; tq[s][3] = f0.w;
            tq[s][4] = f1.x; tq[s][5] = f1.y; tq[s][6] = f1.z; tq[s][7] = f1.w;
        }
#pragma unroll
        for (int j = 0; j < 8; j++) {
            p[0] = fmaf(S[j], kr[0][j], p[0]);
            p[1] = fmaf(S[j], kr[1][j], p[1]);
            p[2] = fmaf(S[j], kr[2][j], p[2]);
            p[3] = fmaf(S[j], kr[3][j], p[3]);
            p[4] = fmaf(S[j], tq[0][j], p[4]);
            p[5] = fmaf(S[j], tq[1][j], p[5]);
            p[6] = fmaf(S[j], tq[2][j], p[6]);
        }
#pragma unroll
        for (int m = 1; m < 8; m <<= 1)
#pragma unroll
            for (int e = 0; e < 7; e++)
                p[e] += __shfl_xor_sync(0xFFFFFFFFu, p[e], m);
        r = p[0]; E1 = p[1]; E2 = p[2]; E3 = p[3];
        F0 = p[4]; F1 = p[5]; F2 = p[6];
    }

    for (int t0 = 0; t0 < TT; t0 += 8) {
#pragma unroll
        for (int p = 0; p < 8; p++) {
            const int t = t0 + p;
            const float* kc  = kr[p];
            const float* kt4 = kr[(p + 4) & 7];
            const float* qt3 = qr[(p + 3) & 3];
            const float* g   = gr[p & 3];
            const float vt = vr[p & 3];
            const float at = ar[p & 3];

            // ---- critical chain ----
            float xg = fmaf(da, r, at);
            float al = fmaf(0.5f, fast_tanh(0.5f * xg), 0.5f);
            float cc = (1.0f - al) * vt;
            float rn = fmaf(al, E1, cc * g[0]);          // r_{t+1}
            float o  = fmaf(al, F0, cc * g[3]);          // S_t . q_t

            // ---- S update + deep-horizon trees (off chain) ----
            float e3 = 0.f, f2 = 0.f;
#pragma unroll
            for (int j = 0; j < 8; j++) {
                S[j] = fmaf(al, S[j], cc * kc[j]);
                e3 = fmaf(S[j], kt4[j], e3);
                f2 = fmaf(S[j], qt3[j], f2);
            }

            // ---- scalar hops (consume last step's tree results late) ----
            float E1n = fmaf(al, E2, cc * g[1]);
            float E2n = fmaf(al, E3, cc * g[2]);
            float F0n = fmaf(al, F1, cc * g[4]);
            float F1n = fmaf(al, F2, cc * g[5]);

            e3 += __shfl_xor_sync(0xFFFFFFFFu, e3, 1);
            f2 += __shfl_xor_sync(0xFFFFFFFFu, f2, 1);
            e3 += __shfl_xor_sync(0xFFFFFFFFu, e3, 2);
            f2 += __shfl_xor_sync(0xFFFFFFFFu, f2, 2);
            e3 += __shfl_xor_sync(0xFFFFFFFFu, e3, 4);
            f2 += __shfl_xor_sync(0xFFFFFFFFu, f2, 4);

            if (c == 0) {
                float sg = fmaf(0.5f, fast_tanh(0.5f * o), 0.5f);
                out[(size_t)(t * BB + b) * NN + i] = o * o * sg;
            }

            r = rn; E1 = E1n; E2 = E2n; E3 = e3;
            F0 = F0n; F1 = F1n; F2 = f2;

            // ---- refill rings ----
            int tk = t + 8;  if (tk > TT - 1) tk = TT - 1;
            int tq_ = t + 7; if (tq_ > TT - 1) tq_ = TT - 1;
            int tg = t + 4;  if (tg > TT - 1) tg = TT - 1;
            ldk(tk, p);
            ldq(tq_, (p + 3) & 3);
            ldg_(tg, p & 3);
            ldva(tg, p & 3);
        }
    }

    float* so = out + (size_t)TT * BB * NN + ((size_t)b * NN + i) * NN + j0;
#pragma unroll
    for (int rji = 0; rji < 8; rji++) so[rji] = S[rji];
}

extern "C" void kernel_launch(void* const* d_in, const int* in_sizes, int n_in,
                              void* d_out, int out_size) {
    const float* x  = (const float*)d_in[0];
    const float* S  = (const float*)d_in[1];
    const float* Wk = (const float*)d_in[2];
    const float* Wv = (const float*)d_in[3];
    const float* Wq = (const float*)d_in[4];
    const float* Wa = (const float*)d_in[5];
    const float* da = (const float*)d_in[6];
    const float* ba = (const float*)d_in[7];
    float* out = (float*)d_out;

    convert_x<<<MT * DD / (256 * 16), 256>>>(x);
    convert_w<<<NC * DD / (256 * 4), 256>>>(Wk, Wv, Wq, Wa);
    dim3 ggrid(MT / GBM, NC / GBN);
    mma_gemm<<<ggrid, 256>>>();
    gram_kernel<<<MT / 8, 256>>>();
    scan_kernel<<<BB * 2, 256>>>(S, da, ba, out);
}

// round 6
// speedup vs baseline: 1.7642x; 1.1588x over previous
#include <cuda_runtime.h>
#include <cuda_bf16.h>
#include <cstdint>

#define TT 2048
#define BB 16
#define DD 1024
#define NN 64
#define MT (TT * BB)      // 32768 rows
#define NC 256            // k|v|q|a packed columns
#define PAD_T 8           // zero padding time-steps (device globals are zeroed)

// ------------------------- device scratch (no allocs allowed) ---------------
__device__ float g_proj[(size_t)(MT + PAD_T * BB) * NC];     // 32 MB + pad (zero)
__device__ float g_gram[(size_t)(MT + PAD_T * BB) * 8];      // 1 MB + pad (zero)
__device__ __nv_bfloat16 g_xhi[(size_t)MT * DD];
__device__ __nv_bfloat16 g_xlo[(size_t)MT * DD];
__device__ __nv_bfloat16 g_whi[(size_t)NC * DD];
__device__ __nv_bfloat16 g_wlo[(size_t)NC * DD];

// ---------------------------------------------------------------------------
// Convert X -> bf16 hi/lo split.
// ---------------------------------------------------------------------------
__global__ __launch_bounds__(256) void convert_x(const float* __restrict__ x) {
    size_t t = (size_t)blockIdx.x * blockDim.x + threadIdx.x;
    size_t base = t * 16;
#pragma unroll
    for (int l = 0; l < 4; l++) {
        float4 v = *(const float4*)(x + base + l * 4);
        __nv_bfloat16 h0 = __float2bfloat16(v.x);
        __nv_bfloat16 h1 = __float2bfloat16(v.y);
        __nv_bfloat16 h2 = __float2bfloat16(v.z);
        __nv_bfloat16 h3 = __float2bfloat16(v.w);
        __nv_bfloat16 l0 = __float2bfloat16(v.x - __bfloat162float(h0));
        __nv_bfloat16 l1 = __float2bfloat16(v.y - __bfloat162float(h1));
        __nv_bfloat16 l2 = __float2bfloat16(v.z - __bfloat162float(h2));
        __nv_bfloat16 l3 = __float2bfloat16(v.w - __bfloat162float(h3));
        __nv_bfloat162 hp0 = __halves2bfloat162(h0, h1);
        __nv_bfloat162 hp1 = __halves2bfloat162(h2, h3);
        __nv_bfloat162 lp0 = __halves2bfloat162(l0, l1);
        __nv_bfloat162 lp1 = __halves2bfloat162(l2, l3);
        *(uint2*)&g_xhi[base + l * 4] = make_uint2(*(uint32_t*)&hp0, *(uint32_t*)&hp1);
        *(uint2*)&g_xlo[base + l * 4] = make_uint2(*(uint32_t*)&lp0, *(uint32_t*)&lp1);
    }
}

__global__ __launch_bounds__(256) void convert_w(
    const float* __restrict__ Wk, const float* __restrict__ Wv,
    const float* __restrict__ Wq, const float* __restrict__ Wa)
{
    int e4 = blockIdx.x * 256 + threadIdx.x;
    int base = e4 * 4;
    int row = base >> 10;
    int colk = base & 1023;
    int cb = row >> 6, n = row & 63;
    const float* W = (cb == 0) ? Wk : (cb == 1) ? Wv : (cb == 2) ? Wq : Wa;
    float4 v = *(const float4*)(W + (size_t)n * DD + colk);
    __nv_bfloat16 h0 = __float2bfloat16(v.x);
    __nv_bfloat16 h1 = __float2bfloat16(v.y);
    __nv_bfloat16 h2 = __float2bfloat16(v.z);
    __nv_bfloat16 h3 = __float2bfloat16(v.w);
    __nv_bfloat16 l0 = __float2bfloat16(v.x - __bfloat162float(h0));
    __nv_bfloat16 l1 = __float2bfloat16(v.y - __bfloat162float(h1));
    __nv_bfloat16 l2 = __float2bfloat16(v.z - __bfloat162float(h2));
    __nv_bfloat16 l3 = __float2bfloat16(v.w - __bfloat162float(h3));
    __nv_bfloat162 hp0 = __halves2bfloat162(h0, h1);
    __nv_bfloat162 hp1 = __halves2bfloat162(h2, h3);
    __nv_bfloat162 lp0 = __halves2bfloat162(l0, l1);
    __nv_bfloat162 lp1 = __halves2bfloat162(l2, l3);
    *(uint2*)&g_whi[(size_t)row * DD + colk] = make_uint2(*(uint32_t*)&hp0, *(uint32_t*)&hp1);
    *(uint2*)&g_wlo[(size_t)row * DD + colk] = make_uint2(*(uint32_t*)&lp0, *(uint32_t*)&lp1);
}

// ---------------------------------------------------------------------------
// Tensor-core GEMM (unchanged): g_proj = X @ Wcat^T, 3x bf16 split.
// ---------------------------------------------------------------------------
#define GBM 128
#define GBN 128
#define GBK 32
#define SA  40

#define MMA16816(d, a, b0v, b1v)                                              \
    asm volatile("mma.sync.aligned.m16n8k16.row.col.f32.bf16.bf16.f32 "       \
                 "{%0,%1,%2,%3}, {%4,%5,%6,%7}, {%8,%9}, {%0,%1,%2,%3};"      \
                 : "+f"(d[0]), "+f"(d[1]), "+f"(d[2]), "+f"(d[3])             \
                 : "r"(a[0]), "r"(a[1]), "r"(a[2]), "r"(a[3]),                \
                   "r"(b0v), "r"(b1v));

__global__ __launch_bounds__(256) void mma_gemm() {
    __shared__ alignas(16) __nv_bfloat16 Ah[GBM * SA];
    __shared__ alignas(16) __nv_bfloat16 Al[GBM * SA];
    __shared__ alignas(16) __nv_bfloat16 Bh[GBN * SA];
    __shared__ alignas(16) __nv_bfloat16 Bl[GBN * SA];

    const int tid = threadIdx.x;
    const int wid = tid >> 5, lane = tid & 31;
    const int wm = wid & 3, wn = wid >> 2;
    const int row0 = blockIdx.x * GBM;
    const int col0 = blockIdx.y * GBN;
    const int g = lane >> 2, tg = lane & 3;

    float acc[2][8][4];
#pragma unroll
    for (int a = 0; a < 2; a++)
#pragma unroll
        for (int b = 0; b < 8; b++)
#pragma unroll
            for (int r = 0; r < 4; r++) acc[a][b][r] = 0.f;

    for (int kb = 0; kb < DD; kb += GBK) {
#pragma unroll
        for (int l = 0; l < 2; l++) {
            int f = tid + 256 * l;
            int r = f >> 2, kc = f & 3;
            size_t ga = (size_t)(row0 + r) * DD + kb + kc * 8;
            size_t gb = (size_t)(col0 + r) * DD + kb + kc * 8;
            *(uint4*)&Ah[r * SA + kc * 8] = *(const uint4*)&g_xhi[ga];
            *(uint4*)&Al[r * SA + kc * 8] = *(const uint4*)&g_xlo[ga];
            *(uint4*)&Bh[r * SA + kc * 8] = *(const uint4*)&g_whi[gb];
            *(uint4*)&Bl[r * SA + kc * 8] = *(const uint4*)&g_wlo[gb];
        }
        __syncthreads();

#pragma unroll
        for (int ks = 0; ks < GBK; ks += 16) {
            uint32_t afh[2][4], afl[2][4];
            const int kk2 = ks + 2 * tg;
#pragma unroll
            for (int ms = 0; ms < 2; ms++) {
                int rr = wm * 32 + ms * 16 + g;
                afh[ms][0] = *(const uint32_t*)&Ah[rr * SA + kk2];
                afh[ms][1] = *(const uint32_t*)&Ah[(rr + 8) * SA + kk2];
                afh[ms][2] = *(const uint32_t*)&Ah[rr * SA + kk2 + 8];
                afh[ms][3] = *(const uint32_t*)&Ah[(rr + 8) * SA + kk2 + 8];
                afl[ms][0] = *(const uint32_t*)&Al[rr * SA + kk2];
                afl[ms][1] = *(const uint32_t*)&Al[(rr + 8) * SA + kk2];
                afl[ms][2] = *(const uint32_t*)&Al[rr * SA + kk2 + 8];
                afl[ms][3] = *(const uint32_t*)&Al[(rr + 8) * SA + kk2 + 8];
            }
#pragma unroll
            for (int ns = 0; ns < 8; ns++) {
                int nr = wn * 64 + ns * 8 + g;
                uint32_t bh0 = *(const uint32_t*)&Bh[nr * SA + kk2];
                uint32_t bh1 = *(const uint32_t*)&Bh[nr * SA + kk2 + 8];
                uint32_t bl0 = *(const uint32_t*)&Bl[nr * SA + kk2];
                uint32_t bl1 = *(const uint32_t*)&Bl[nr * SA + kk2 + 8];
#pragma unroll
                for (int ms = 0; ms < 2; ms++) {
                    MMA16816(acc[ms][ns], afh[ms], bh0, bh1);
                    MMA16816(acc[ms][ns], afh[ms], bl0, bl1);
                    MMA16816(acc[ms][ns], afl[ms], bh0, bh1);
                }
            }
        }
        __syncthreads();
    }

#pragma unroll
    for (int ms = 0; ms < 2; ms++)
#pragma unroll
        for (int ns = 0; ns < 8; ns++) {
            int m = row0 + wm * 32 + ms * 16 + g;
            int n = col0 + wn * 64 + ns * 8 + tg * 2;
            *(float2*)&g_proj[(size_t)m * NC + n] =
                make_float2(acc[ms][ns][0], acc[ms][ns][1]);
            *(float2*)&g_proj[(size_t)(m + 8) * NC + n] =
                make_float2(acc[ms][ns][2], acc[ms][ns][3]);
        }
}

// ---------------------------------------------------------------------------
// Gram kernel: row r = t*16+b ->
//   [kk1,kk2,kk3,kk4, kq0,kq1,kq2,kq3],  kkd = k_t.k_{t+d}, kqd = k_t.q_{t+d}
// Reads beyond MT hit zero padding -> terms naturally 0. One warp per row.
// ---------------------------------------------------------------------------
__global__ __launch_bounds__(256) void gram_kernel() {
    const int wid = threadIdx.x >> 5, lane = threadIdx.x & 31;
    const int row = blockIdx.x * 8 + wid;
    const float* P0 = g_proj + (size_t)row * NC;

    float k0a = P0[lane], k0b = P0[32 + lane];
    float d[8];
#pragma unroll
    for (int dd = 0; dd < 4; dd++) {
        const float* Pd = g_proj + (size_t)(row + (dd + 1) * BB) * NC;
        d[dd] = k0a * Pd[lane] + k0b * Pd[32 + lane];                  // kk_{d+1}
        const float* Pq = g_proj + (size_t)(row + dd * BB) * NC;
        d[4 + dd] = k0a * Pq[128 + lane] + k0b * Pq[160 + lane];       // kq_d
    }
#pragma unroll
    for (int m = 1; m < 32; m <<= 1)
#pragma unroll
        for (int e = 0; e < 8; e++)
            d[e] += __shfl_xor_sync(0xFFFFFFFFu, d[e], m);

    if (lane == 0) {
        float4* G = (float4*)&g_gram[(size_t)row * 8];
        G[0] = make_float4(d[0], d[1], d[2], d[3]);
        G[1] = make_float4(d[4], d[5], d[6], d[7]);
    }
}

// ---------------------------------------------------------------------------
// Scan v5: reduction-free, 16 lanes/row, pointer-offset refills, no clamps.
// Scalars per row: r = S.k_t, E1..E4 = S.k_{t+1..4}, F0..F3 = S.q_{t..t+3}.
// Trees refresh deep horizon (S.k_{t+5}, S.q_{t+4}); results pass 3 scalar
// hops before reaching r -> plenty of slack for the 4-level shfl trees.
// 64 blocks x 256 thr = 64 SMs, 2 warps/SMSP. S = 4 floats/thread.
// ---------------------------------------------------------------------------
__device__ __forceinline__ float fast_tanh(float x) {
    float r;
    asm("tanh.approx.f32 %0, %1;" : "=f"(r) : "f"(x));
    return r;
}

__global__ __launch_bounds__(256) void scan_kernel(
    const float* __restrict__ S_in,
    const float* __restrict__ dA,
    const float* __restrict__ bA,
    float* __restrict__ out)
{
    const int b  = blockIdx.x >> 2;
    const int rb = blockIdx.x & 3;
    const int il = threadIdx.x >> 4;     // local row 0..15
    const int i  = rb * 16 + il;         // global row 0..63
    const int c  = threadIdx.x & 15;     // lane within row
    const int j0 = c << 2;

    float S[4];
    {
        const float* sp = S_in + ((size_t)b * NN + i) * NN + j0;
#pragma unroll
        for (int r = 0; r < 4; r++) S[r] = sp[r];
    }
    const float da = dA[i];
    const float ba_ = bA[i];

    // base pointers (per-thread slices)
    const float* Pk = g_proj + (size_t)b * NC + j0;            // k slice
    const float* Pq = g_proj + (size_t)b * NC + 128 + j0;      // q slice
    const float* Pv = g_proj + (size_t)b * NC + 64 + i;        // v scalar
    const float* Pa = g_proj + (size_t)b * NC + 192 + i;       // a scalar
    const float* Pg = g_gram + (size_t)b * 8;                  // gram (8 floats)
    const size_t STEPP = (size_t)BB * NC;                      // proj row stride
    const size_t STEPG = (size_t)BB * 8;

    float kr[8][4], qr[4][4], gr[4][8], vr[4], ar[4];

    auto ldk = [&](int t, int slot) {
        float4 f = *(const float4*)(Pk + (size_t)t * STEPP);
        kr[slot][0] = f.x; kr[slot][1] = f.y; kr[slot][2] = f.z; kr[slot][3] = f.w;
    };
    auto ldq = [&](int t, int slot) {
        float4 f = *(const float4*)(Pq + (size_t)t * STEPP);
        qr[slot][0] = f.x; qr[slot][1] = f.y; qr[slot][2] = f.z; qr[slot][3] = f.w;
    };
    auto ldg_ = [&](int t, int slot) {
        const float* G = Pg + (size_t)t * STEPG;
        float4 g0 = *(const float4*)G;
        float4 g1 = *(const float4*)(G + 4);
        gr[slot][0] = g0.x; gr[slot][1] = g0.y; gr[slot][2] = g0.z; gr[slot][3] = g0.w;
        gr[slot][4] = g1.x; gr[slot][5] = g1.y; gr[slot][6] = g1.z; gr[slot][7] = g1.w;
    };
    auto ldva = [&](int t, int slot) {
        vr[slot] = Pv[(size_t)t * STEPP];
        ar[slot] = Pa[(size_t)t * STEPP] + ba_;
    };

    // preload rings: k_0..k_7 ; q_4..q_7 ; gram/v/a 0..3
#pragma unroll
    for (int s = 0; s < 8; s++) ldk(s, s);
#pragma unroll
    for (int s = 0; s < 4; s++) { ldq(s + 4, s); ldg_(s, s); ldva(s, s); }

    // prologue: r=S.k0, E1..E4=S.k_{1..4}, F0..F3=S.q_{0..3}
    float r, E1, E2, E3, E4, F0, F1, F2, F3;
    {
        float tq[4][4];
#pragma unroll
        for (int s = 0; s < 4; s++) {
            float4 f = *(const float4*)(Pq + (size_t)s * STEPP);
            tq[s][0] = f.x; tq[s][1] = f.y; tq[s][2] = f.z; tq[s][3] = f.w;
        }
        float p[9] = {0,0,0,0,0,0,0,0,0};
#pragma unroll
        for (int j = 0; j < 4; j++) {
            p[0] = fmaf(S[j], kr[0][j], p[0]);
            p[1] = fmaf(S[j], kr[1][j], p[1]);
            p[2] = fmaf(S[j], kr[2][j], p[2]);
            p[3] = fmaf(S[j], kr[3][j], p[3]);
            p[4] = fmaf(S[j], kr[4][j], p[4]);
            p[5] = fmaf(S[j], tq[0][j], p[5]);
            p[6] = fmaf(S[j], tq[1][j], p[6]);
            p[7] = fmaf(S[j], tq[2][j], p[7]);
            p[8] = fmaf(S[j], tq[3][j], p[8]);
        }
#pragma unroll
        for (int m = 1; m < 16; m <<= 1)
#pragma unroll
            for (int e = 0; e < 9; e++)
                p[e] += __shfl_xor_sync(0xFFFFFFFFu, p[e], m);
        r = p[0]; E1 = p[1]; E2 = p[2]; E3 = p[3]; E4 = p[4];
        F0 = p[5]; F1 = p[6]; F2 = p[7]; F3 = p[8];
    }

    for (int t0 = 0; t0 < TT; t0 += 8) {
#pragma unroll
        for (int p = 0; p < 8; p++) {
            const int t = t0 + p;
            const float* kc  = kr[p];
            const float* kt5 = kr[(p + 5) & 7];
            const float* qt4 = qr[p & 3];
            const float* g   = gr[p & 3];
            const float vt = vr[p & 3];
            const float at = ar[p & 3];

            // ---- critical chain ----
            float xg = fmaf(da, r, at);
            float al = fmaf(0.5f, fast_tanh(0.5f * xg), 0.5f);
            float cc = (1.0f - al) * vt;
            float rn = fmaf(al, E1, cc * g[0]);          // S_t.k_{t+1}
            float o  = fmaf(al, F0, cc * g[4]);          // S_t.q_t

            // ---- S update + deep-horizon trees ----
            float e4 = 0.f, f3 = 0.f;
#pragma unroll
            for (int j = 0; j < 4; j++) {
                S[j] = fmaf(al, S[j], cc * kc[j]);
                e4 = fmaf(S[j], kt5[j], e4);
                f3 = fmaf(S[j], qt4[j], f3);
            }

            // ---- scalar hops ----
            float E1n = fmaf(al, E2, cc * g[1]);
            float E2n = fmaf(al, E3, cc * g[2]);
            float E3n = fmaf(al, E4, cc * g[3]);
            float F0n = fmaf(al, F1, cc * g[5]);
            float F1n = fmaf(al, F2, cc * g[6]);
            float F2n = fmaf(al, F3, cc * g[7]);

            e4 += __shfl_xor_sync(0xFFFFFFFFu, e4, 1);
            f3 += __shfl_xor_sync(0xFFFFFFFFu, f3, 1);
            e4 += __shfl_xor_sync(0xFFFFFFFFu, e4, 2);
            f3 += __shfl_xor_sync(0xFFFFFFFFu, f3, 2);
            e4 += __shfl_xor_sync(0xFFFFFFFFu, e4, 4);
            f3 += __shfl_xor_sync(0xFFFFFFFFu, f3, 4);
            e4 += __shfl_xor_sync(0xFFFFFFFFu, e4, 8);
            f3 += __shfl_xor_sync(0xFFFFFFFFu, f3, 8);

            if (c == 0) {
                float sg = fmaf(0.5f, fast_tanh(0.5f * o), 0.5f);
                out[(size_t)(t * BB + b) * NN + i] = o * o * sg;
            }

            r = rn; E1 = E1n; E2 = E2n; E3 = E3n; E4 = e4;
            F0 = F0n; F1 = F1n; F2 = F2n; F3 = f3;

            // ---- ring refills (padding makes OOB reads zero; no clamps) ----
            ldk(t + 8, p);
            ldq(t + 8, p & 3);
            ldg_(t + 4, p & 3);
            ldva(t + 4, p & 3);
        }
    }

    float* so = out + (size_t)TT * BB * NN + ((size_t)b * NN + i) * NN + j0;
#pragma unroll
    for (int rji = 0; rji < 4; rji++) so[rji] = S[rji];
}

extern "C" void kernel_launch(void* const* d_in, const int* in_sizes, int n_in,
                              void* d_out, int out_size) {
    const float* x  = (const float*)d_in[0];
    const float* S  = (const float*)d_in[1];
    const float* Wk = (const float*)d_in[2];
    const float* Wv = (const float*)d_in[3];
    const float* Wq = (const float*)d_in[4];
    const float* Wa = (const float*)d_in[5];
    const float* da = (const float*)d_in[6];
    const float* ba = (const float*)d_in[7];
    float* out = (float*)d_out;

    convert_x<<<MT * DD / (256 * 16), 256>>>(x);
    convert_w<<<NC * DD / (256 * 4), 256>>>(Wk, Wv, Wq, Wa);
    dim3 ggrid(MT / GBM, NC / GBN);
    mma_gemm<<<ggrid, 256>>>();
    gram_kernel<<<MT / 8, 256>>>();
    scan_kernel<<<BB * 4, 256>>>(S, da, ba, out);
}